// round 11
// baseline (speedup 1.0000x reference)
#include <cuda_runtime.h>
#include <math.h>
#include <stdint.h>

#define B_   256
#define T_   256
#define INSZ 512
#define HD   1024
#define NBLK 128
#define NTHR 256

typedef unsigned long long u64;

__device__ float g_h[2][B_ * 4 * HD];
__device__ float g_pred[2][B_ * INSZ];

__device__ unsigned g_count;
__device__ volatile unsigned g_sense;

__device__ __forceinline__ void grid_barrier(unsigned& ls)
{
    __syncthreads();
    if (threadIdx.x == 0) {
        unsigned s = ls ^ 1u;
        __threadfence();
        if (atomicAdd(&g_count, 1u) == NBLK - 1) {
            g_count = 0;
            __threadfence();
            g_sense = s;            // release
        } else {
            while (g_sense != s) { __nanosleep(32); }
        }
        __threadfence();            // acquire
        ls = s;
    }
    __syncthreads();
}

// ---- packed f32x2 helpers ----
__device__ __forceinline__ u64 pack2(float lo, float hi)
{ u64 r; asm("mov.b64 %0, {%1, %2};" : "=l"(r) : "f"(lo), "f"(hi)); return r; }
__device__ __forceinline__ void unpack2(u64 v, float& lo, float& hi)
{ asm("mov.b64 {%0, %1}, %2;" : "=f"(lo), "=f"(hi) : "l"(v)); }
__device__ __forceinline__ void ffma2(u64& d, u64 a, u64 b)
{ asm("fma.rn.f32x2 %0, %1, %2, %0;" : "+l"(d) : "l"(a), "l"(b)); }
__device__ __forceinline__ u64 addf2(u64 a, u64 b)
{ u64 r; asm("add.rn.f32x2 %0, %1, %2;" : "=l"(r) : "l"(a), "l"(b)); return r; }

// smem byte offsets (all tiles natural [row][k] layout, float4 columns, XOR swizzle)
#define OFF_AS  0          // float4 [64][16]   = 16384 B
#define OFF_WU  16384      // float4 [32][16]   =  8192 B
#define OFF_WR  24576
#define OFF_WN  32768
#define OFF_RED 40960      // u64 [128][33]     = 33792 B
#define SMEMB   74752

// ---------------------------------------------------------------------------
// 3-gate GEMM: 32j x 64b tile, 256 threads, chunk K=64, 2-way k-split.
// Tiles stored [row][k] (no transpose). A swizzle: col ^ ((row>>2)&7).
// Inner loop: 4-k groups, k-vectorized float4 reads, operand packing in regs.
// ---------------------------------------------------------------------------
__device__ __forceinline__ void accum3(
    const float* __restrict__ A, int astride,
    const float* __restrict__ W, int K, int nk,
    u64 (&au)[2][4], u64 (&ar)[2][4], u64 (&an)[2][4],
    int tx, int ty, int qg, int tid,
    float4* As4, float4* Wu4, float4* Wr4, float4* Wn4)
{
    float4 pa[4], pu[2], pr[2], pn[2];

    // prologue: prefetch chunk 0
#pragma unroll
    for (int i = 0; i < 4; i++) {
        int lin = tid + i * 256;
        pa[i] = __ldcg((const float4*)(A + (size_t)(lin >> 4) * astride + (lin & 15) * 4));
    }
#pragma unroll
    for (int i = 0; i < 2; i++) {
        int lin = tid + i * 256;
        size_t ro = (size_t)(lin >> 4) * K + (lin & 15) * 4;
        pu[i] = *(const float4*)(W + ro);
        pr[i] = *(const float4*)(W + (size_t)HD * K + ro);
        pn[i] = *(const float4*)(W + (size_t)(2 * HD) * K + ro);
    }

    for (int k0 = 0; k0 < nk; k0 += 64) {
        __syncthreads();
#pragma unroll
        for (int i = 0; i < 4; i++) {
            int lin = tid + i * 256;
            int b2 = lin >> 4, c = lin & 15;
            As4[b2 * 16 + (c ^ ((b2 >> 2) & 7))] = pa[i];
        }
#pragma unroll
        for (int i = 0; i < 2; i++) {
            int lin = tid + i * 256;
            int jj = lin >> 4, c = lin & 15;
            int sc = jj * 16 + (c ^ ((jj >> 2) & 7));
            Wu4[sc] = pu[i]; Wr4[sc] = pr[i]; Wn4[sc] = pn[i];
        }
        __syncthreads();
        int kn = k0 + 64;
        if (kn < nk) {
#pragma unroll
            for (int i = 0; i < 4; i++) {
                int lin = tid + i * 256;
                pa[i] = __ldcg((const float4*)(A + (size_t)(lin >> 4) * astride + (kn + (lin & 15) * 4)));
            }
#pragma unroll
            for (int i = 0; i < 2; i++) {
                int lin = tid + i * 256;
                size_t ro = (size_t)(lin >> 4) * K + (kn + (lin & 15) * 4);
                pu[i] = *(const float4*)(W + ro);
                pr[i] = *(const float4*)(W + (size_t)HD * K + ro);
                pn[i] = *(const float4*)(W + (size_t)(2 * HD) * K + ro);
            }
        }
        // compute: this half's 8 groups of 4 k
#pragma unroll
        for (int g = 0; g < 8; g++) {
            int c = qg + g;
            u64 Apk[4][4];
#pragma unroll
            for (int i = 0; i < 4; i++) {
                float4 av = As4[(ty * 4 + i) * 16 + (c ^ (ty & 7))];
                const float* ap = &av.x;
#pragma unroll
                for (int k2 = 0; k2 < 4; k2++) Apk[i][k2] = pack2(ap[k2], ap[k2]);
            }
            {
                float4 wv0 = Wu4[(tx * 4 + 0) * 16 + (c ^ tx)];
                float4 wv1 = Wu4[(tx * 4 + 1) * 16 + (c ^ tx)];
                float4 wv2 = Wu4[(tx * 4 + 2) * 16 + (c ^ tx)];
                float4 wv3 = Wu4[(tx * 4 + 3) * 16 + (c ^ tx)];
                const float *q0 = &wv0.x, *q1 = &wv1.x, *q2 = &wv2.x, *q3 = &wv3.x;
#pragma unroll
                for (int k2 = 0; k2 < 4; k2++) {
                    u64 p0 = pack2(q0[k2], q1[k2]);
                    u64 p1 = pack2(q2[k2], q3[k2]);
#pragma unroll
                    for (int i = 0; i < 4; i++) {
                        ffma2(au[0][i], Apk[i][k2], p0);
                        ffma2(au[1][i], Apk[i][k2], p1);
                    }
                }
            }
            {
                float4 wv0 = Wr4[(tx * 4 + 0) * 16 + (c ^ tx)];
                float4 wv1 = Wr4[(tx * 4 + 1) * 16 + (c ^ tx)];
                float4 wv2 = Wr4[(tx * 4 + 2) * 16 + (c ^ tx)];
                float4 wv3 = Wr4[(tx * 4 + 3) * 16 + (c ^ tx)];
                const float *q0 = &wv0.x, *q1 = &wv1.x, *q2 = &wv2.x, *q3 = &wv3.x;
#pragma unroll
                for (int k2 = 0; k2 < 4; k2++) {
                    u64 p0 = pack2(q0[k2], q1[k2]);
                    u64 p1 = pack2(q2[k2], q3[k2]);
#pragma unroll
                    for (int i = 0; i < 4; i++) {
                        ffma2(ar[0][i], Apk[i][k2], p0);
                        ffma2(ar[1][i], Apk[i][k2], p1);
                    }
                }
            }
            {
                float4 wv0 = Wn4[(tx * 4 + 0) * 16 + (c ^ tx)];
                float4 wv1 = Wn4[(tx * 4 + 1) * 16 + (c ^ tx)];
                float4 wv2 = Wn4[(tx * 4 + 2) * 16 + (c ^ tx)];
                float4 wv3 = Wn4[(tx * 4 + 3) * 16 + (c ^ tx)];
                const float *q0 = &wv0.x, *q1 = &wv1.x, *q2 = &wv2.x, *q3 = &wv3.x;
#pragma unroll
                for (int k2 = 0; k2 < 4; k2++) {
                    u64 p0 = pack2(q0[k2], q1[k2]);
                    u64 p1 = pack2(q2[k2], q3[k2]);
#pragma unroll
                    for (int i = 0; i < 4; i++) {
                        ffma2(an[0][i], Apk[i][k2], p0);
                        ffma2(an[1][i], Apk[i][k2], p1);
                    }
                }
            }
        }
    }
}

// Pred: 16o x 64b tile, 256 threads, chunk K=64, 2-way k-split.
// W tile [16][64] swizzle: col ^ ((row>>1)&7). Acc packed over b-pairs.
__device__ __forceinline__ void accum1(
    const float* __restrict__ A, int astride,
    const float* __restrict__ W, int wstride, int nk,
    u64 (&acc)[2][2],            // [o][bpair]
    int tx, int ty, int qg, int tid,
    float4* As4, float4* Ws4)
{
    float4 pa[4], pw;

#pragma unroll
    for (int i = 0; i < 4; i++) {
        int lin = tid + i * 256;
        pa[i] = __ldcg((const float4*)(A + (size_t)(lin >> 4) * astride + (lin & 15) * 4));
    }
    pw = *(const float4*)(W + (size_t)(tid >> 4) * wstride + (tid & 15) * 4);

    for (int k0 = 0; k0 < nk; k0 += 64) {
        __syncthreads();
#pragma unroll
        for (int i = 0; i < 4; i++) {
            int lin = tid + i * 256;
            int b2 = lin >> 4, c = lin & 15;
            As4[b2 * 16 + (c ^ ((b2 >> 2) & 7))] = pa[i];
        }
        {
            int jj = tid >> 4, c = tid & 15;   // jj 0..15 (256 threads exactly)
            Ws4[jj * 16 + (c ^ ((jj >> 1) & 7))] = pw;
        }
        __syncthreads();
        int kn = k0 + 64;
        if (kn < nk) {
#pragma unroll
            for (int i = 0; i < 4; i++) {
                int lin = tid + i * 256;
                pa[i] = __ldcg((const float4*)(A + (size_t)(lin >> 4) * astride + (kn + (lin & 15) * 4)));
            }
            pw = *(const float4*)(W + (size_t)(tid >> 4) * wstride + (kn + (tid & 15) * 4));
        }
#pragma unroll
        for (int g = 0; g < 8; g++) {
            int c = qg + g;
            float4 av0 = As4[(ty * 4 + 0) * 16 + (c ^ (ty & 7))];
            float4 av1 = As4[(ty * 4 + 1) * 16 + (c ^ (ty & 7))];
            float4 av2 = As4[(ty * 4 + 2) * 16 + (c ^ (ty & 7))];
            float4 av3 = As4[(ty * 4 + 3) * 16 + (c ^ (ty & 7))];
            float4 wa = Ws4[(tx * 2 + 0) * 16 + (c ^ tx)];
            float4 wb = Ws4[(tx * 2 + 1) * 16 + (c ^ tx)];
            const float *a0 = &av0.x, *a1 = &av1.x, *a2 = &av2.x, *a3 = &av3.x;
            const float *w0 = &wa.x, *w1 = &wb.x;
#pragma unroll
            for (int k2 = 0; k2 < 4; k2++) {
                u64 ab0 = pack2(a0[k2], a1[k2]);
                u64 ab1 = pack2(a2[k2], a3[k2]);
                u64 W0 = pack2(w0[k2], w0[k2]);
                u64 W1 = pack2(w1[k2], w1[k2]);
                ffma2(acc[0][0], W0, ab0); ffma2(acc[0][1], W0, ab1);
                ffma2(acc[1][0], W1, ab0); ffma2(acc[1][1], W1, ab1);
            }
        }
    }
}

// ---------------------------------------------------------------------------
// One persistent kernel. grid = 128 blocks, 256 threads.
// ---------------------------------------------------------------------------
__global__ void __launch_bounds__(NTHR) sgru_kernel(
    const float* __restrict__ xb, const float* __restrict__ h0,
    const float* __restrict__ Wx, const float* __restrict__ bx,
    const float* __restrict__ Wh, const float* __restrict__ bh,
    const float* __restrict__ Wo, const float* __restrict__ bo,
    float* __restrict__ out)
{
    extern __shared__ __align__(16) char smx[];
    float4* As4 = (float4*)(smx + OFF_AS);
    float4* Wu4 = (float4*)(smx + OFF_WU);
    float4* Wr4 = (float4*)(smx + OFF_WR);
    float4* Wn4 = (float4*)(smx + OFF_WN);
    u64* red = (u64*)(smx + OFF_RED);

    int tid = threadIdx.x;
    int bid = blockIdx.x;
    int tid2 = tid & 127, half = tid >> 7, qg = half * 8;
    unsigned ls = g_sense;

    // ---- init: h0 -> g_h[0] ----
    {
        int g = bid * NTHR + tid;
        const float4* s4 = (const float4*)h0;
        float4* d4 = (float4*)g_h[0];
#pragma unroll 1
        for (int i = g; i < B_ * 4 * HD / 4; i += NBLK * NTHR) d4[i] = s4[i];
    }
    grid_barrier(ls);

#pragma unroll 1
    for (int t = 0; t < T_; t++) {
        int rd = t & 1, wr = rd ^ 1;
#pragma unroll 1
        for (int s = 0; s < 4; s++) {
            int wi = (s == 3) ? 2 : s;   // faithful to the source bug

            const float* x;
            int xstride;
            if (s == 0) { x = xb + (size_t)t * INSZ; xstride = T_ * INSZ; }
            else        { x = g_pred[(s - 1) & 1];   xstride = INSZ; }

            // ===== gate phase: 32 j-tiles (32) x 4 b-tiles (64) =====
            {
                int tx = tid2 & 7, ty = tid2 >> 3;   // 8 x 4j = 32j, 16 x 4b = 64b
                int j0 = (bid & 31) * 32;
                int b0 = (bid >> 5) * 64;
                const float* Wxp = Wx + (size_t)wi * 3 * HD * INSZ + (size_t)j0 * INSZ;
                const float* Whp = Wh + (size_t)wi * 3 * HD * HD + (size_t)j0 * HD;
                const float* bx3 = bx + wi * 3 * HD;
                const float* bh3 = bh + wi * 3 * HD;
                const float* hrd = g_h[rd] + s * HD;
                float* hwr = g_h[wr] + s * HD;

                u64 au[2][4], ar[2][4], axn[2][4], ahn[2][4];
                if (half == 0) {
#pragma unroll
                    for (int p = 0; p < 2; p++) {
                        int jg = j0 + tx * 4 + p * 2;
                        u64 bu = pack2(bx3[jg] + bh3[jg], bx3[jg + 1] + bh3[jg + 1]);
                        u64 br = pack2(bx3[HD + jg] + bh3[HD + jg],
                                       bx3[HD + jg + 1] + bh3[HD + jg + 1]);
                        u64 bxn = pack2(bx3[2 * HD + jg], bx3[2 * HD + jg + 1]);
                        u64 bhn = pack2(bh3[2 * HD + jg], bh3[2 * HD + jg + 1]);
#pragma unroll
                        for (int i = 0; i < 4; i++) {
                            au[p][i] = bu; ar[p][i] = br;
                            axn[p][i] = bxn; ahn[p][i] = bhn;
                        }
                    }
                } else {
#pragma unroll
                    for (int p = 0; p < 2; p++)
#pragma unroll
                        for (int i = 0; i < 4; i++) {
                            au[p][i] = 0; ar[p][i] = 0;
                            axn[p][i] = 0; ahn[p][i] = 0;
                        }
                }
                accum3(x + (size_t)b0 * xstride, xstride, Wxp, INSZ, INSZ,
                       au, ar, axn, tx, ty, qg, tid, As4, Wu4, Wr4, Wn4);
                accum3(hrd + (size_t)b0 * (4 * HD), 4 * HD, Whp, HD, HD,
                       au, ar, ahn, tx, ty, qg, tid, As4, Wu4, Wr4, Wn4);

                // cross-half reduction (32 u64 per thread, single round)
                __syncthreads();
                if (half) {
                    u64* rp = red + (size_t)tid2 * 33;
#pragma unroll
                    for (int p = 0; p < 2; p++)
#pragma unroll
                        for (int i = 0; i < 4; i++) {
                            rp[p * 4 + i] = au[p][i];
                            rp[8 + p * 4 + i] = ar[p][i];
                            rp[16 + p * 4 + i] = axn[p][i];
                            rp[24 + p * 4 + i] = ahn[p][i];
                        }
                }
                __syncthreads();
                if (!half) {
                    u64* rp = red + (size_t)tid2 * 33;
#pragma unroll
                    for (int p = 0; p < 2; p++)
#pragma unroll
                        for (int i = 0; i < 4; i++) {
                            au[p][i] = addf2(au[p][i], rp[p * 4 + i]);
                            ar[p][i] = addf2(ar[p][i], rp[8 + p * 4 + i]);
                            axn[p][i] = addf2(axn[p][i], rp[16 + p * 4 + i]);
                            ahn[p][i] = addf2(ahn[p][i], rp[24 + p * 4 + i]);
                        }
#pragma unroll
                    for (int i = 0; i < 4; i++) {
                        int b = b0 + ty * 4 + i;
                        int jg = j0 + tx * 4;
                        float4 hold = __ldcg((const float4*)(hrd + (size_t)b * (4 * HD) + jg));
                        float ho[4] = {hold.x, hold.y, hold.z, hold.w};
                        float uv[4], rv[4], xnv[4], hnv[4];
#pragma unroll
                        for (int p = 0; p < 2; p++) {
                            unpack2(au[p][i], uv[p * 2], uv[p * 2 + 1]);
                            unpack2(ar[p][i], rv[p * 2], rv[p * 2 + 1]);
                            unpack2(axn[p][i], xnv[p * 2], xnv[p * 2 + 1]);
                            unpack2(ahn[p][i], hnv[p * 2], hnv[p * 2 + 1]);
                        }
                        float4 hv;
                        float* hvp = &hv.x;
#pragma unroll
                        for (int jj = 0; jj < 4; jj++) {
                            float u = 1.0f / (1.0f + expf(-uv[jj]));
                            float r = 1.0f / (1.0f + expf(-rv[jj]));
                            float n = tanhf(xnv[jj] + r * hnv[jj]);
                            hvp[jj] = u * ho[jj] + (1.0f - u) * n;
                        }
                        *(float4*)(hwr + (size_t)b * (4 * HD) + jg) = hv;
                    }
                }
            }
            grid_barrier(ls);

            // ===== pred phase: 32 o-tiles (16) x 4 b-tiles (64) =====
            {
                int tx = tid2 & 7, ty = tid2 >> 3;   // 8 x 2o = 16o, 16 x 4b = 64b
                int o0 = (bid & 31) * 16;
                int b0 = (bid >> 5) * 64;
                const float* Wop = Wo + (size_t)wi * INSZ * (HD + INSZ) + (size_t)o0 * (HD + INSZ);
                const float* bop = bo + wi * INSZ;
                const float* hn = g_h[wr] + s * HD;

                u64 acc[2][2];   // [o][bpair]
                if (half == 0) {
                    acc[0][0] = acc[0][1] = pack2(bop[o0 + tx * 2], bop[o0 + tx * 2]);
                    acc[1][0] = acc[1][1] = pack2(bop[o0 + tx * 2 + 1], bop[o0 + tx * 2 + 1]);
                } else {
                    acc[0][0] = acc[0][1] = 0;
                    acc[1][0] = acc[1][1] = 0;
                }

                accum1(x + (size_t)b0 * xstride, xstride,
                       Wop, HD + INSZ, INSZ, acc, tx, ty, qg, tid, As4, Wu4);
                accum1(hn + (size_t)b0 * (4 * HD), 4 * HD,
                       Wop + INSZ, HD + INSZ, HD, acc, tx, ty, qg, tid, As4, Wu4);

                __syncthreads();
                if (half) {
                    u64* rp = red + (size_t)tid2 * 33;
                    rp[0] = acc[0][0]; rp[1] = acc[0][1];
                    rp[2] = acc[1][0]; rp[3] = acc[1][1];
                }
                __syncthreads();
                if (!half) {
                    u64* rp = red + (size_t)tid2 * 33;
                    acc[0][0] = addf2(acc[0][0], rp[0]);
                    acc[0][1] = addf2(acc[0][1], rp[1]);
                    acc[1][0] = addf2(acc[1][0], rp[2]);
                    acc[1][1] = addf2(acc[1][1], rp[3]);

                    float* outp; int ostr;
                    if (s == 3) { outp = out + (size_t)t * INSZ; ostr = T_ * INSZ; }
                    else        { outp = g_pred[s & 1];          ostr = INSZ; }

                    float o0b[4], o1b[4];
                    unpack2(acc[0][0], o0b[0], o0b[1]); unpack2(acc[0][1], o0b[2], o0b[3]);
                    unpack2(acc[1][0], o1b[0], o1b[1]); unpack2(acc[1][1], o1b[2], o1b[3]);
#pragma unroll
                    for (int i = 0; i < 4; i++) {
                        int b = b0 + ty * 4 + i;
                        float2 v = make_float2(o0b[i], o1b[i]);
                        *(float2*)(outp + (size_t)b * ostr + (o0 + tx * 2)) = v;
                    }
                }
            }
            grid_barrier(ls);
        }
    }

    // ---- copy final h (in g_h[0]) to out tail ----
    {
        int g = bid * NTHR + tid;
        const float4* s4 = (const float4*)g_h[0];
        float4* d4 = (float4*)(out + (size_t)B_ * T_ * INSZ);
#pragma unroll 1
        for (int i = g; i < B_ * 4 * HD / 4; i += NBLK * NTHR) d4[i] = __ldcg(s4 + i);
    }

    // ---- log_softmax over each 512-wide pred row ----
    {
        int w = tid >> 5, ln = tid & 31;      // 8 warps per block
        int gw = bid * 8 + w;
#pragma unroll 1
        for (int r = gw; r < B_ * T_; r += NBLK * 8) {
            float* p = out + (size_t)r * INSZ;
            float v[16];
            float m = -1e30f;
#pragma unroll
            for (int i = 0; i < 16; i++) {
                v[i] = __ldcg(p + ln + i * 32);
                m = fmaxf(m, v[i]);
            }
#pragma unroll
            for (int off = 16; off > 0; off >>= 1)
                m = fmaxf(m, __shfl_xor_sync(0xffffffffu, m, off));
            float sm = 0.0f;
#pragma unroll
            for (int i = 0; i < 16; i++) sm += expf(v[i] - m);
#pragma unroll
            for (int off = 16; off > 0; off >>= 1)
                sm += __shfl_xor_sync(0xffffffffu, sm, off);
            float lsv = m + logf(sm);
#pragma unroll
            for (int i = 0; i < 16; i++) p[ln + i * 32] = v[i] - lsv;
        }
    }
}

// ---------------------------------------------------------------------------
extern "C" void kernel_launch(void* const* d_in, const int* in_sizes, int n_in,
                              void* d_out, int out_size)
{
    const float* xb = (const float*)d_in[0];
    const float* h0 = (const float*)d_in[1];
    const float* Wx = (const float*)d_in[2];
    const float* bx = (const float*)d_in[3];
    const float* Wh = (const float*)d_in[4];
    const float* bh = (const float*)d_in[5];
    const float* Wo = (const float*)d_in[6];
    const float* bo = (const float*)d_in[7];
    float* out = (float*)d_out;

    cudaFuncSetAttribute(sgru_kernel, cudaFuncAttributeMaxDynamicSharedMemorySize, SMEMB);
    sgru_kernel<<<NBLK, NTHR, SMEMB>>>(xb, h0, Wx, bx, Wh, bh, Wo, bo, out);
}

// round 12
// speedup vs baseline: 1.6022x; 1.6022x over previous
#include <cuda_runtime.h>
#include <math.h>
#include <stdint.h>

#define B_   256
#define T_   256
#define INSZ 512
#define HD   1024
#define NBLK 128
#define NTHR 256
#define NCH  24

typedef unsigned long long u64;

// k-major (transposed) operand buffers, built once per launch in init pass
__device__ float g_xT[T_ * INSZ * B_];          // [t][k][b]
__device__ float g_hT[2][4 * HD * B_];          // [pp][s*HD+j][b]
__device__ float g_pT[2][INSZ * B_];            // [pp][o][b]
__device__ float g_WxT[4 * INSZ * 3 * HD];      // [wi][k][J]  J in 0..3071
__device__ float g_WhT[4 * HD * 3 * HD];
__device__ float g_WoT[4 * (HD + INSZ) * INSZ]; // [wi][k][o]

__device__ unsigned g_count;
__device__ volatile unsigned g_sense;

__device__ __forceinline__ void grid_barrier(unsigned& ls)
{
    __syncthreads();
    if (threadIdx.x == 0) {
        unsigned s = ls ^ 1u;
        __threadfence();
        if (atomicAdd(&g_count, 1u) == NBLK - 1) {
            g_count = 0;
            __threadfence();
            g_sense = s;
        } else {
            while (g_sense != s) { __nanosleep(32); }
        }
        __threadfence();
        ls = s;
    }
    __syncthreads();
}

__device__ __forceinline__ u64 pack2(float lo, float hi)
{ u64 r; asm("mov.b64 %0, {%1, %2};" : "=l"(r) : "f"(lo), "f"(hi)); return r; }
__device__ __forceinline__ void unpack2(u64 v, float& lo, float& hi)
{ asm("mov.b64 {%0, %1}, %2;" : "=f"(lo), "=f"(hi) : "l"(v)); }
__device__ __forceinline__ void ffma2(u64& d, u64 a, u64 b)
{ asm("fma.rn.f32x2 %0, %1, %2, %0;" : "+l"(d) : "l"(a), "l"(b)); }

__device__ __forceinline__ uint32_t smem_u32(const void* p)
{ uint32_t a; asm("{ .reg .u64 t; cvta.to.shared.u64 t, %1; cvt.u32.u64 %0, t; }" : "=r"(a) : "l"(p)); return a; }

__device__ __forceinline__ void cp16(uint32_t dst, const float* src)
{ asm volatile("cp.async.cg.shared.global [%0], [%1], 16;" :: "r"(dst), "l"(src)); }

#define CPCOMMIT() asm volatile("cp.async.commit_group;" ::: "memory")
#define CPWAIT1()  asm volatile("cp.async.wait_group 1;" ::: "memory")
#define CPWAIT0()  asm volatile("cp.async.wait_group 0;" ::: "memory")

// stage layout: A tile [64k][64b] floats @0 (16384 B); W tiles @16384
// gate: 3 x [64k][32j] (8192 B each); pred: [64k][16o] (4096 B)
#define STG_B 40960
#define SMEMB (3 * STG_B)

// ---------------- cp.async issue helpers ----------------
__device__ __forceinline__ void issue_gate(uint32_t stg, const float* Ap, const float* Wp, int tid)
{
#pragma unroll
    for (int i = 0; i < 4; i++) {
        int idx = tid + i * 256, row = idx >> 4, seg = idx & 15;
        cp16(stg + row * 256 + seg * 16, Ap + (size_t)row * B_ + seg * 4);
    }
#pragma unroll
    for (int i = 0; i < 6; i++) {
        int idx = tid + i * 256, tile = idx >> 9, rem = idx & 511, row = rem >> 3, seg = rem & 7;
        cp16(stg + 16384 + tile * 8192 + row * 128 + seg * 16,
             Wp + (size_t)row * (3 * HD) + tile * HD + seg * 4);
    }
}

__device__ __forceinline__ void issue_pred(uint32_t stg, const float* Ap, const float* Wp, int tid)
{
#pragma unroll
    for (int i = 0; i < 4; i++) {
        int idx = tid + i * 256, row = idx >> 4, seg = idx & 15;
        cp16(stg + row * 256 + seg * 16, Ap + (size_t)row * B_ + seg * 4);
    }
    { int row = tid >> 2, seg = tid & 3;
      cp16(stg + 16384 + row * 64 + seg * 16, Wp + (size_t)row * INSZ + seg * 4); }
}

__device__ __forceinline__ const float* gate_A(const float* xb_, const float* hb, int c, int b0)
{ return (c < 8) ? xb_ + (size_t)(c * 64) * B_ + b0 : hb + (size_t)((c - 8) * 64) * B_ + b0; }
__device__ __forceinline__ const float* gate_W(const float* wx, const float* wh, int c, int j0)
{ return (c < 8) ? wx + (size_t)(c * 64) * (3 * HD) + j0 : wh + (size_t)((c - 8) * 64) * (3 * HD) + j0; }

// ---------------- compute ----------------
__device__ __forceinline__ void gate_compute(const char* stg, int tx, int ty,
    u64 (&au)[2][2], u64 (&ar)[2][2], u64 (&an)[2][2])
{
    const float* As = (const float*)stg;
    const char* W = stg + 16384;
#pragma unroll 8
    for (int kk = 0; kk < 64; kk++) {
        float2 a2 = *(const float2*)(As + kk * 64 + ty * 2);
        u64 A0 = pack2(a2.x, a2.x), A1 = pack2(a2.y, a2.y);
        ulonglong2 wu = *(const ulonglong2*)(W + kk * 128 + tx * 16);
        ulonglong2 wr = *(const ulonglong2*)(W + 8192 + kk * 128 + tx * 16);
        ulonglong2 wn = *(const ulonglong2*)(W + 16384 + kk * 128 + tx * 16);
        ffma2(au[0][0], A0, wu.x); ffma2(au[1][0], A0, wu.y);
        ffma2(au[0][1], A1, wu.x); ffma2(au[1][1], A1, wu.y);
        ffma2(ar[0][0], A0, wr.x); ffma2(ar[1][0], A0, wr.y);
        ffma2(ar[0][1], A1, wr.x); ffma2(ar[1][1], A1, wr.y);
        ffma2(an[0][0], A0, wn.x); ffma2(an[1][0], A0, wn.y);
        ffma2(an[0][1], A1, wn.x); ffma2(an[1][1], A1, wn.y);
    }
}

__device__ __forceinline__ void pred_compute(const char* stg, int tx, int ty, u64 (&acc)[2])
{
    const float* As = (const float*)stg;
    const char* W = stg + 16384;
#pragma unroll 8
    for (int kk = 0; kk < 64; kk++) {
        float2 a2 = *(const float2*)(As + kk * 64 + ty * 2);
        u64 wv = *(const u64*)(W + kk * 64 + tx * 8);
        ffma2(acc[0], pack2(a2.x, a2.x), wv);
        ffma2(acc[1], pack2(a2.y, a2.y), wv);
    }
}

// ---------------------------------------------------------------------------
__global__ void __launch_bounds__(NTHR) sgru_kernel(
    const float* __restrict__ xb, const float* __restrict__ h0,
    const float* __restrict__ Wx, const float* __restrict__ bx,
    const float* __restrict__ Wh, const float* __restrict__ bh,
    const float* __restrict__ Wo, const float* __restrict__ bo,
    float* __restrict__ out)
{
    extern __shared__ __align__(16) char smx[];
    const uint32_t smb = smem_u32(smx);
    const int tid = threadIdx.x, bid = blockIdx.x;
    const int tx = tid & 7, ty = tid >> 3;   // 8 x (4j|2o), 32 x 2b
    unsigned ls = g_sense;

    // ================= init pass: build k-major copies =================
    {
        const long GT = NBLK * NTHR;
        const long g0 = (long)bid * NTHR + tid;
        for (long d = g0; d < (long)T_ * INSZ * B_; d += GT) {
            int b = (int)(d & 255); long rest = d >> 8;
            int k = (int)(rest & 511); int tt = (int)(rest >> 9);
            g_xT[d] = __ldg(xb + ((size_t)b * T_ + tt) * INSZ + k);
        }
        for (long d = g0; d < (long)4 * INSZ * 3 * HD; d += GT) {
            int J = (int)(d % 3072); long rest = d / 3072;
            int k = (int)(rest & 511); int wi = (int)(rest >> 9);
            g_WxT[d] = __ldg(Wx + ((size_t)wi * 3072 + J) * INSZ + k);
        }
        for (long d = g0; d < (long)4 * HD * 3 * HD; d += GT) {
            int J = (int)(d % 3072); long rest = d / 3072;
            int k = (int)(rest & 1023); int wi = (int)(rest >> 10);
            g_WhT[d] = __ldg(Wh + ((size_t)wi * 3072 + J) * HD + k);
        }
        for (long d = g0; d < (long)4 * (HD + INSZ) * INSZ; d += GT) {
            int o = (int)(d & 511); long rest = d >> 9;
            int k = (int)(rest % 1536); int wi = (int)(rest / 1536);
            g_WoT[d] = __ldg(Wo + ((size_t)wi * INSZ + o) * (HD + INSZ) + k);
        }
        for (long d = g0; d < (long)4 * HD * B_; d += GT) {
            int b = (int)(d & 255); long rest = d >> 8;
            int j = (int)(rest & 1023); int s = (int)(rest >> 10);
            g_hT[0][d] = __ldg(h0 + ((size_t)b * 4 + s) * HD + j);
        }
    }
    grid_barrier(ls);

#pragma unroll 1
    for (int t = 0; t < T_; t++) {
        int rd = t & 1, wr = rd ^ 1;
#pragma unroll 1
        for (int s = 0; s < 4; s++) {
            const int wi = (s == 3) ? 2 : s;   // faithful to the source bug
            const float* xbase = (s == 0) ? g_xT + (size_t)t * INSZ * B_
                                          : g_pT[(s - 1) & 1];
            const float* hrdT = g_hT[rd] + (size_t)s * HD * B_;
            float*       hwrT = g_hT[wr] + (size_t)s * HD * B_;
            const float* wxT = g_WxT + (size_t)wi * INSZ * 3 * HD;
            const float* whT = g_WhT + (size_t)wi * HD * 3 * HD;
            const float* woT = g_WoT + (size_t)wi * (HD + INSZ) * INSZ;

            const int j0 = (bid & 31) * 32;
            const int o0 = (bid & 31) * 16;
            const int b0 = (bid >> 5) * 64;

            // ================= GATE =================
            {
                issue_gate(smb, gate_A(xbase, hrdT, 0, b0), gate_W(wxT, whT, 0, j0), tid); CPCOMMIT();
                issue_gate(smb + STG_B, gate_A(xbase, hrdT, 1, b0), gate_W(wxT, whT, 1, j0), tid); CPCOMMIT();

                u64 au[2][2], ar[2][2], axn[2][2], ahn[2][2];
                const float* bx3 = bx + wi * 3 * HD;
                const float* bh3 = bh + wi * 3 * HD;
#pragma unroll
                for (int p = 0; p < 2; p++) {
                    int jg = j0 + tx * 4 + p * 2;
                    u64 bu = pack2(bx3[jg] + bh3[jg], bx3[jg + 1] + bh3[jg + 1]);
                    u64 br = pack2(bx3[HD + jg] + bh3[HD + jg], bx3[HD + jg + 1] + bh3[HD + jg + 1]);
                    u64 bxn = pack2(bx3[2 * HD + jg], bx3[2 * HD + jg + 1]);
                    u64 bhn = pack2(bh3[2 * HD + jg], bh3[2 * HD + jg + 1]);
                    au[p][0] = au[p][1] = bu; ar[p][0] = ar[p][1] = br;
                    axn[p][0] = axn[p][1] = bxn; ahn[p][0] = ahn[p][1] = bhn;
                }
#pragma unroll 1
                for (int c = 0; c < NCH; c++) {
                    if (c < NCH - 1) CPWAIT1(); else CPWAIT0();
                    __syncthreads();
                    if (c + 2 < NCH) {
                        issue_gate(smb + ((c + 2) % 3) * STG_B,
                                   gate_A(xbase, hrdT, c + 2, b0),
                                   gate_W(wxT, whT, c + 2, j0), tid);
                        CPCOMMIT();
                    }
                    if (c < 8)
                        gate_compute(smx + (c % 3) * STG_B, tx, ty, au, ar, axn);
                    else
                        gate_compute(smx + (c % 3) * STG_B, tx, ty, au, ar, ahn);
                }
                // epilogue: every thread owns 4j x 2b outputs
#pragma unroll
                for (int i = 0; i < 2; i++) {
                    int b = b0 + ty * 2 + i;
                    int jg = j0 + tx * 4;
                    float uv[4], rv[4], xnv[4], hnv[4];
#pragma unroll
                    for (int p = 0; p < 2; p++) {
                        unpack2(au[p][i], uv[p * 2], uv[p * 2 + 1]);
                        unpack2(ar[p][i], rv[p * 2], rv[p * 2 + 1]);
                        unpack2(axn[p][i], xnv[p * 2], xnv[p * 2 + 1]);
                        unpack2(ahn[p][i], hnv[p * 2], hnv[p * 2 + 1]);
                    }
#pragma unroll
                    for (int jj = 0; jj < 4; jj++) {
                        float u = 1.0f / (1.0f + expf(-uv[jj]));
                        float r = 1.0f / (1.0f + expf(-rv[jj]));
                        float n = tanhf(xnv[jj] + r * hnv[jj]);
                        float ho = __ldcg(hrdT + (size_t)(jg + jj) * B_ + b);
                        hwrT[(size_t)(jg + jj) * B_ + b] = u * ho + (1.0f - u) * n;
                    }
                }
            }
            // pred prologue (x-chunks + immutable Wo): safe before the barrier
            issue_pred(smb, gate_A(xbase, g_hT[wr] + (size_t)s * HD * B_, 0, b0),
                       woT + 0 * INSZ + o0, tid); CPCOMMIT();
            issue_pred(smb + STG_B, gate_A(xbase, g_hT[wr] + (size_t)s * HD * B_, 1, b0),
                       woT + (size_t)64 * INSZ + o0, tid); CPCOMMIT();
            grid_barrier(ls);

            // ================= PRED =================
            {
                const float* hnT = g_hT[wr] + (size_t)s * HD * B_;
                const float* bop = bo + wi * INSZ;
                u64 acc[2];
                acc[0] = acc[1] = pack2(bop[o0 + tx * 2], bop[o0 + tx * 2 + 1]);
#pragma unroll 1
                for (int c = 0; c < NCH; c++) {
                    if (c < NCH - 1) CPWAIT1(); else CPWAIT0();
                    __syncthreads();
                    if (c + 2 < NCH) {
                        issue_pred(smb + ((c + 2) % 3) * STG_B,
                                   gate_A(xbase, hnT, c + 2, b0),
                                   woT + (size_t)((c + 2) * 64) * INSZ + o0, tid);
                        CPCOMMIT();
                    }
                    pred_compute(smx + (c % 3) * STG_B, tx, ty, acc);
                }
                int o = o0 + tx * 2;
#pragma unroll
                for (int i = 0; i < 2; i++) {
                    int b = b0 + ty * 2 + i;
                    float v0, v1;
                    unpack2(acc[i], v0, v1);
                    if (s == 3) {
                        *(float2*)(out + ((size_t)b * T_ + t) * INSZ + o) = make_float2(v0, v1);
                    } else {
                        float* pT = g_pT[s & 1];
                        pT[(size_t)o * B_ + b] = v0;
                        pT[(size_t)(o + 1) * B_ + b] = v1;
                    }
                }
            }
            grid_barrier(ls);
        }
    }

    // ---- final h copy-out (hT[0] -> out tail, standard layout) ----
    {
        const long GT = NBLK * NTHR;
        for (long d = (long)bid * NTHR + tid; d < (long)B_ * 4 * HD; d += GT) {
            int j = (int)(d & 1023); long rest = d >> 10;
            int s = (int)(rest & 3); int b = (int)(rest >> 2);
            out[(size_t)B_ * T_ * INSZ + d] = __ldcg(&g_hT[0][((size_t)s * HD + j) * B_ + b]);
        }
    }
    // ---- log_softmax over each 512-wide pred row ----
    {
        int w = tid >> 5, ln = tid & 31;
        int gw = bid * 8 + w;
#pragma unroll 1
        for (int r = gw; r < B_ * T_; r += NBLK * 8) {
            float* p = out + (size_t)r * INSZ;
            float v[16], m = -1e30f;
#pragma unroll
            for (int i = 0; i < 16; i++) { v[i] = __ldcg(p + ln + i * 32); m = fmaxf(m, v[i]); }
#pragma unroll
            for (int o = 16; o > 0; o >>= 1) m = fmaxf(m, __shfl_xor_sync(~0u, m, o));
            float sv = 0.0f;
#pragma unroll
            for (int i = 0; i < 16; i++) sv += expf(v[i] - m);
#pragma unroll
            for (int o = 16; o > 0; o >>= 1) sv += __shfl_xor_sync(~0u, sv, o);
            float lv = m + logf(sv);
#pragma unroll
            for (int i = 0; i < 16; i++) p[ln + i * 32] = v[i] - lv;
        }
    }
}

// ---------------------------------------------------------------------------
extern "C" void kernel_launch(void* const* d_in, const int* in_sizes, int n_in,
                              void* d_out, int out_size)
{
    cudaFuncSetAttribute(sgru_kernel, cudaFuncAttributeMaxDynamicSharedMemorySize, SMEMB);
    sgru_kernel<<<NBLK, NTHR, SMEMB>>>(
        (const float*)d_in[0], (const float*)d_in[1], (const float*)d_in[2],
        (const float*)d_in[3], (const float*)d_in[4], (const float*)d_in[5],
        (const float*)d_in[6], (const float*)d_in[7], (float*)d_out);
}